// round 12
// baseline (speedup 1.0000x reference)
#include <cuda_runtime.h>
#include <math.h>

// Gating: x[B=8,S=8192,H=512] f32, gate_w[E=4,H], gate_b[E]
// Outputs concatenated in d_out (float32):
//   [0, 4T)   sparse_logits   [4T,6T) indices(float)   [6T,10T) gate_logit
// T = B*S = 65536.

#define HIDDEN 512
#define NEXP 4
#define NTOK 65536
#define TPW 2                          // tokens per warp
#define WARPS 8                        // warps per block (256 threads)
#define TILE_TOK (TPW * WARPS)         // 16 tokens per block
#define NBLOCKS (NTOK / TILE_TOK)      // 4096

__global__ __launch_bounds__(256, 6) void gating_kernel(
    const float* __restrict__ x,
    const float* __restrict__ gate_w,
    const float* __restrict__ gate_b,
    float* __restrict__ out)
{
    __shared__ float4 sgw[NEXP][HIDDEN / 4];   // 8KB
    __shared__ float sgb[NEXP];

    int tid    = threadIdx.x;
    int warpid = tid >> 5;
    int lane   = tid & 31;
    int half   = lane >> 4;            // 0/1: which token this half finishes
    int hl     = lane & 15;

    int tbase = blockIdx.x * TILE_TOK + warpid * TPW;

    // ---- front-batch both tokens' x (8 LDG.128/thread), before the barrier ----
    const float4* xr = (const float4*)(x + (size_t)tbase * HIDDEN);
    float4 v[TPW][4];
#pragma unroll
    for (int t = 0; t < TPW; t++)
#pragma unroll
        for (int i = 0; i < 4; i++)
            v[t][i] = xr[t * (HIDDEN / 4) + lane + i * 32];

    // stage weights while x loads are in flight (2 iters/thread at 256 threads)
    for (int i = tid; i < NEXP * (HIDDEN / 4); i += 256) {
        ((float4*)sgw)[i] = ((const float4*)gate_w)[i];
    }
    if (tid < NEXP) sgb[tid] = gate_b[tid];
    __syncthreads();

    // ---- compute: full-warp dot products, weights read once per chunk ----
    float a[TPW][NEXP];
#pragma unroll
    for (int t = 0; t < TPW; t++)
#pragma unroll
        for (int e = 0; e < NEXP; e++) a[t][e] = 0.f;

#pragma unroll
    for (int i = 0; i < 4; i++) {
        int h = lane + i * 32;
        float4 w0 = sgw[0][h];
        float4 w1 = sgw[1][h];
        float4 w2 = sgw[2][h];
        float4 w3 = sgw[3][h];
#pragma unroll
        for (int t = 0; t < TPW; t++) {
            float4 vv = v[t][i];
            a[t][0] += vv.x * w0.x + vv.y * w0.y + vv.z * w0.z + vv.w * w0.w;
            a[t][1] += vv.x * w1.x + vv.y * w1.y + vv.z * w1.z + vv.w * w1.w;
            a[t][2] += vv.x * w2.x + vv.y * w2.y + vv.z * w2.z + vv.w * w2.w;
            a[t][3] += vv.x * w3.x + vv.y * w3.y + vv.z * w3.z + vv.w * w3.w;
        }
    }

    // ---- fold reduce ----
    // stage 1: offset-16 butterfly on all 8 values
#pragma unroll
    for (int t = 0; t < TPW; t++)
#pragma unroll
        for (int e = 0; e < NEXP; e++)
            a[t][e] += __shfl_xor_sync(0xFFFFFFFFu, a[t][e], 16);

    // each half-warp adopts its token's 4 values, finishes with offsets 8..1
    float c0 = half ? a[1][0] : a[0][0];
    float c1 = half ? a[1][1] : a[0][1];
    float c2 = half ? a[1][2] : a[0][2];
    float c3 = half ? a[1][3] : a[0][3];
#pragma unroll
    for (int o = 8; o > 0; o >>= 1) {
        c0 += __shfl_xor_sync(0xFFFFFFFFu, c0, o);
        c1 += __shfl_xor_sync(0xFFFFFFFFu, c1, o);
        c2 += __shfl_xor_sync(0xFFFFFFFFu, c2, o);
        c3 += __shfl_xor_sync(0xFFFFFFFFu, c3, o);
    }

    // lanes 0 and 16 each finish one token
    if (hl == 0) {
        int token = tbase + half;

        float l[NEXP];
        l[0] = c0 + sgb[0];
        l[1] = c1 + sgb[1];
        l[2] = c2 + sgb[2];
        l[3] = c3 + sgb[3];

        // gate_logit (raw logits)
        float4* glog = (float4*)(out + (size_t)6 * NTOK);
        glog[token] = make_float4(l[0], l[1], l[2], l[3]);

        // top-2 (earlier index wins ties, matching jax top_k)
        int i0 = 0; float m0 = l[0];
#pragma unroll
        for (int e = 1; e < NEXP; e++) { if (l[e] > m0) { m0 = l[e]; i0 = e; } }
        int i1 = -1; float m1 = -INFINITY;
#pragma unroll
        for (int e = 0; e < NEXP; e++) {
            if (e != i0 && l[e] > m1) { m1 = l[e]; i1 = e; }
        }

        // softmax over {m0, m1}
        float e1 = __expf(m1 - m0);
        float inv = 1.0f / (1.0f + e1);

        float sp[NEXP] = {0.f, 0.f, 0.f, 0.f};
        sp[i0] = inv;
        sp[i1] = e1 * inv;
        float4* spv = (float4*)out;
        spv[token] = make_float4(sp[0], sp[1], sp[2], sp[3]);

        float2* idx = (float2*)(out + (size_t)4 * NTOK);
        idx[token] = make_float2((float)i0, (float)i1);
    }
}

extern "C" void kernel_launch(void* const* d_in, const int* in_sizes, int n_in,
                              void* d_out, int out_size)
{
    const float* x      = (const float*)d_in[0];
    const float* gate_w = (const float*)d_in[1];
    const float* gate_b = (const float*)d_in[2];
    float* out = (float*)d_out;

    gating_kernel<<<NBLOCKS, 256>>>(x, gate_w, gate_b, out);
}

// round 13
// speedup vs baseline: 1.1795x; 1.1795x over previous
#include <cuda_runtime.h>
#include <math.h>

// Gating: x[B=8,S=8192,H=512] f32, gate_w[E=4,H], gate_b[E]
// Outputs concatenated in d_out (float32):
//   [0, 4T)   sparse_logits   [4T,6T) indices(float)   [6T,10T) gate_logit
// T = B*S = 65536.

#define HIDDEN 512
#define NEXP 4
#define NTOK 65536
#define TPW 4                          // tokens per warp
#define WARPS 8                        // 256 threads
#define TILE_TOK (TPW * WARPS)         // 32 tokens per block
#define NBLOCKS (NTOK / TILE_TOK)      // 2048

__global__ __launch_bounds__(256, 5) void gating_kernel(
    const float* __restrict__ x,
    const float* __restrict__ gate_w,
    const float* __restrict__ gate_b,
    float* __restrict__ out)
{
    __shared__ float4 sgw[NEXP][HIDDEN / 4];   // 8KB
    __shared__ float sgb[NEXP];

    int tid    = threadIdx.x;
    int warpid = tid >> 5;
    int lane   = tid & 31;
    int half   = lane >> 4;            // bit4
    int quart  = (lane >> 3) & 1;      // bit3

    int tbase = blockIdx.x * TILE_TOK + warpid * TPW;
    const float4* xr = (const float4*)(x + (size_t)tbase * HIDDEN);

    // ---- prefetch chunk 0's x for all 4 tokens, before the barrier ----
    float4 v[TPW];
#pragma unroll
    for (int t = 0; t < TPW; t++)
        v[t] = xr[t * (HIDDEN / 4) + lane];

    // stage weights while x loads are in flight (2 iters/thread)
    for (int i = tid; i < NEXP * (HIDDEN / 4); i += 256) {
        ((float4*)sgw)[i] = ((const float4*)gate_w)[i];
    }
    if (tid < NEXP) sgb[tid] = gate_b[tid];
    __syncthreads();

    float acc[TPW][NEXP];
#pragma unroll
    for (int t = 0; t < TPW; t++)
#pragma unroll
        for (int e = 0; e < NEXP; e++) acc[t][e] = 0.f;

    // ---- chunk-major: weights loaded once per chunk, shared by 4 tokens ----
#pragma unroll
    for (int i = 0; i < 4; i++) {
        int h = lane + i * 32;
        if (i > 0) {
#pragma unroll
            for (int t = 0; t < TPW; t++)
                v[t] = xr[t * (HIDDEN / 4) + h];
        }
        // expert-major: one weight float4 live at a time
#pragma unroll
        for (int e = 0; e < NEXP; e++) {
            float4 w = sgw[e][h];
#pragma unroll
            for (int t = 0; t < TPW; t++) {
                acc[t][e] += v[t].x * w.x + v[t].y * w.y
                           + v[t].z * w.z + v[t].w * w.w;
            }
        }
    }

    // ---- deep fold reduce ----
    // stage 1: offset-16 on all 16 values
#pragma unroll
    for (int t = 0; t < TPW; t++)
#pragma unroll
        for (int e = 0; e < NEXP; e++)
            acc[t][e] += __shfl_xor_sync(0xFFFFFFFFu, acc[t][e], 16);

    // halves adopt 2 tokens each: half 0 -> tokens {0,1}, half 1 -> {2,3}
    float b[2][NEXP];
#pragma unroll
    for (int j = 0; j < 2; j++)
#pragma unroll
        for (int e = 0; e < NEXP; e++)
            b[j][e] = half ? acc[2 + j][e] : acc[j][e];

    // stage 2: offset-8 on 8 values
#pragma unroll
    for (int j = 0; j < 2; j++)
#pragma unroll
        for (int e = 0; e < NEXP; e++)
            b[j][e] += __shfl_xor_sync(0xFFFFFFFFu, b[j][e], 8);

    // quarters adopt 1 token each
    float c[NEXP];
#pragma unroll
    for (int e = 0; e < NEXP; e++)
        c[e] = quart ? b[1][e] : b[0][e];

    // stages 3-5: offsets 4,2,1 on 4 values
#pragma unroll
    for (int o = 4; o > 0; o >>= 1)
#pragma unroll
        for (int e = 0; e < NEXP; e++)
            c[e] += __shfl_xor_sync(0xFFFFFFFFu, c[e], o);

    // lanes 0,8,16,24 each finish one token (token = tbase + lane/8)
    if ((lane & 7) == 0) {
        int token = tbase + (lane >> 3);

        float l[NEXP];
#pragma unroll
        for (int e = 0; e < NEXP; e++) l[e] = c[e] + sgb[e];

        // gate_logit (raw logits)
        float4* glog = (float4*)(out + (size_t)6 * NTOK);
        glog[token] = make_float4(l[0], l[1], l[2], l[3]);

        // top-2 (earlier index wins ties, matching jax top_k)
        int i0 = 0; float m0 = l[0];
#pragma unroll
        for (int e = 1; e < NEXP; e++) { if (l[e] > m0) { m0 = l[e]; i0 = e; } }
        int i1 = -1; float m1 = -INFINITY;
#pragma unroll
        for (int e = 0; e < NEXP; e++) {
            if (e != i0 && l[e] > m1) { m1 = l[e]; i1 = e; }
        }

        // softmax over {m0, m1}
        float e1 = __expf(m1 - m0);
        float inv = 1.0f / (1.0f + e1);

        float sp[NEXP] = {0.f, 0.f, 0.f, 0.f};
        sp[i0] = inv;
        sp[i1] = e1 * inv;
        float4* spv = (float4*)out;
        spv[token] = make_float4(sp[0], sp[1], sp[2], sp[3]);

        float2* idx = (float2*)(out + (size_t)4 * NTOK);
        idx[token] = make_float2((float)i0, (float)i1);
    }
}

extern "C" void kernel_launch(void* const* d_in, const int* in_sizes, int n_in,
                              void* d_out, int out_size)
{
    const float* x      = (const float*)d_in[0];
    const float* gate_w = (const float*)d_in[1];
    const float* gate_b = (const float*)d_in[2];
    float* out = (float*)d_out;

    gating_kernel<<<NBLOCKS, 256>>>(x, gate_w, gate_b, out);
}